// round 9
// baseline (speedup 1.0000x reference)
#include <cuda_runtime.h>

#define NB    16
#define NCP   64
#define NTPL  2048
#define HD    10
#define NSTEP 6
#define DTC   0.2f
#define LOG2E 1.4426950408889634f

#define SH_NCTA 512           // shoot CTAs (bids 0..511) -- all wave-1 resident
#define FL_NCTA (NB * (NTPL / 16))   // 2048 flow CTAs

typedef unsigned long long ull;

// ---- scratch (static device globals; no allocation) ----
__device__ float2 g_P[NSTEP + 1][NB * NCP];
__device__ float2 g_Q[NSTEP + 1][NB * NCP];
__device__ unsigned g_bar_count;
__device__ unsigned g_bar_gen;    // = number of completed shoot steps

// ---------------- packed f32x2 helpers ----------------
__device__ __forceinline__ ull pack2(float lo, float hi) {
    ull d; asm("mov.b64 %0, {%1,%2};" : "=l"(d) : "f"(lo), "f"(hi)); return d;
}
__device__ __forceinline__ void unpack2(ull d, float& lo, float& hi) {
    asm("mov.b64 {%0,%1}, %2;" : "=f"(lo), "=f"(hi) : "l"(d));
}
__device__ __forceinline__ ull fma2(ull a, ull b, ull c) {
    ull d; asm("fma.rn.f32x2 %0, %1, %2, %3;" : "=l"(d) : "l"(a), "l"(b), "l"(c)); return d;
}
__device__ __forceinline__ ull add2(ull a, ull b) {
    ull d; asm("add.rn.f32x2 %0, %1, %2;" : "=l"(d) : "l"(a), "l"(b)); return d;
}
__device__ __forceinline__ float tanhfast(float x) {
    float y; asm("tanh.approx.f32 %0, %1;" : "=f"(y) : "f"(x)); return y;
}
__device__ __forceinline__ float ex2f(float x) {
    float y; asm("ex2.approx.f32 %0, %1;" : "=f"(y) : "f"(x)); return y;
}

// ---------------- reset (per replay) ----------------
__global__ void reset_kernel() {
    if (threadIdx.x == 0) { g_bar_count = 0; g_bar_gen = 0; }
}

// ---------------- grid barrier among the SH_NCTA shoot CTAs ----------------
__device__ __forceinline__ void grid_bar_shoot() {
    __syncthreads();
    if (threadIdx.x == 0) {
        __threadfence();
        unsigned gen = *(volatile unsigned*)&g_bar_gen;
        unsigned prev = atomicAdd(&g_bar_count, 1u);
        if (prev == SH_NCTA - 1) {
            g_bar_count = 0;
            __threadfence();
            atomicExch(&g_bar_gen, gen + 1u);
        } else {
            while (*(volatile unsigned*)&g_bar_gen == gen) { }
            __threadfence();
        }
    }
    __syncthreads();
}

// ------------------------------------------------------------------
// MLP forward + 2-tangent JVP (tangent dirs = rows da, db of W1)
// ------------------------------------------------------------------
__device__ __forceinline__ void mlp_jac(
    float z0, float z1, float z2, float z3, int da, int db,
    const float* __restrict__ sW1, const float* __restrict__ sb1,
    const float* __restrict__ sW2, const float* __restrict__ sb2,
    const float* __restrict__ sW3, const float* __restrict__ sb3,
    float o[3], float ja[3], float jb[3]) {
    float h1[HD], ta[HD], tb[HD];
#pragma unroll
    for (int n = 0; n < HD; n++) {
        float u = sb1[n] + z0 * sW1[n] + z1 * sW1[10 + n] + z2 * sW1[20 + n] + z3 * sW1[30 + n];
        float h = tanhfast(u);
        float g = 1.0f - h * h;
        h1[n] = h;
        ta[n] = g * sW1[da * 10 + n];
        tb[n] = g * sW1[db * 10 + n];
    }
    float u2[HD], s2a[HD], s2b[HD];
#pragma unroll
    for (int m = 0; m < HD; m++) { u2[m] = sb2[m]; s2a[m] = 0.f; s2b[m] = 0.f; }
#pragma unroll
    for (int n = 0; n < HD; n++) {
        float h = h1[n], aa = ta[n], bb = tb[n];
#pragma unroll
        for (int m = 0; m < HD; m++) {
            float w = sW2[n * 10 + m];
            u2[m] += h * w;
            s2a[m] += aa * w;
            s2b[m] += bb * w;
        }
    }
#pragma unroll
    for (int c = 0; c < 3; c++) { o[c] = sb3[c]; ja[c] = 0.f; jb[c] = 0.f; }
#pragma unroll
    for (int m = 0; m < HD; m++) {
        float h = tanhfast(u2[m]);
        float g = 1.0f - h * h;
        float aa = s2a[m] * g, bb = s2b[m] * g;
#pragma unroll
        for (int c = 0; c < 3; c++) {
            float w = sW3[m * 3 + c];
            o[c] += h * w;
            ja[c] += aa * w;
            jb[c] += bb * w;
        }
    }
}

// ------------------------------------------------------------------
// packed forward MLP: W2 in REGISTERS (hot); layer-3 weights + b2 from
// shared (cold broadcast LDS). W3 cols 1,2 prescaled by log2e -> ex2.
// ------------------------------------------------------------------
__device__ __forceinline__ void mlp2s(
    const ull u1p[5], const ull W2p[50],
    const ull* sb2p, const float* sW3c0, const ull* sW3p12,
    float b3c0, ull b3p12,
    float& o0, ull& o12) {
    ull u2p[5];
#pragma unroll
    for (int i = 0; i < 5; i++) u2p[i] = sb2p[i];
#pragma unroll
    for (int i = 0; i < 5; i++) {
        float lo, hi; unpack2(u1p[i], lo, hi);
        float h0 = tanhfast(lo), h1 = tanhfast(hi);
        ull hp0 = pack2(h0, h0), hp1 = pack2(h1, h1);
        int n0 = (2 * i) * 5, n1 = (2 * i + 1) * 5;
#pragma unroll
        for (int m = 0; m < 5; m++) u2p[m] = fma2(hp0, W2p[n0 + m], u2p[m]);
#pragma unroll
        for (int m = 0; m < 5; m++) u2p[m] = fma2(hp1, W2p[n1 + m], u2p[m]);
    }
    o0 = b3c0; o12 = b3p12;
#pragma unroll
    for (int i = 0; i < 5; i++) {
        float lo, hi; unpack2(u2p[i], lo, hi);
        float h0 = tanhfast(lo), h1 = tanhfast(hi);
        ull hp0 = pack2(h0, h0), hp1 = pack2(h1, h1);
        o12 = fma2(hp0, sW3p12[2 * i], o12);
        o12 = fma2(hp1, sW3p12[2 * i + 1], o12);
        o0 = fmaf(h1, sW3c0[2 * i + 1], fmaf(h0, sW3c0[2 * i], o0));
    }
}

// ------------------------------------------------------------------
// FUSED kernel: bids [0,512) = shoot role, [512, 2560) = flow role.
// Shoot: 512 CTAs x 64 thr, 2 a-points/CTA, 4 mlp_jac/thread/step,
//        grid barrier (among shoot CTAs only) after every step; the
//        barrier generation g_bar_gen doubles as the step-ready flag.
// Flow : round-6 body; step 0 reads cp/q0 directly, step k>=1 waits
//        for g_bar_gen >= k then reads g_P[k]/g_Q[k].
// ------------------------------------------------------------------
__global__ void __launch_bounds__(64, 6) fused_all(
    const float* __restrict__ q0, const float* __restrict__ tpl,
    const float* __restrict__ cp, float* __restrict__ dout,
    const float* __restrict__ W1, const float* __restrict__ b1,
    const float* __restrict__ W2, const float* __restrict__ b2,
    const float* __restrict__ W3, const float* __restrict__ b3) {
    int t = threadIdx.x;
    int bid = blockIdx.x;
    const float2* cp2 = (const float2*)cp;
    const float2* q02 = (const float2*)q0;

    if (bid < SH_NCTA) {
        // ======================= SHOOT ROLE =======================
        __shared__ float hW1[40], hb1[10], hW2[100], hb2[10], hW3[30], hb3[3];
        __shared__ float red[2][2][4];   // [a_local][warp][4]
        for (int i = t; i < 40; i += 64) hW1[i] = W1[i];
        for (int i = t; i < 100; i += 64) hW2[i] = W2[i];
        for (int i = t; i < 30; i += 64) hW3[i] = W3[i];
        if (t < 10) { hb1[t] = b1[t]; hb2[t] = b2[t]; }
        if (t < 3) hb3[t] = b3[t];
        __syncthreads();

        int b = bid >> 5;
        int a0 = (bid & 31) << 1;
        int warp = t >> 5;

        for (int k = 0; k < NSTEP; k++) {
            float2 pj, qj;
            if (k == 0) { pj = __ldg(&cp2[t]); qj = __ldg(&q02[b * NCP + t]); }
            else        { pj = g_P[k][b * NCP + t]; qj = g_Q[k][b * NCP + t]; }

#pragma unroll
            for (int aa = 0; aa < 2; aa++) {
                int a = a0 + aa;
                float2 pa, qa;
                if (k == 0) { pa = __ldg(&cp2[a]); qa = __ldg(&q02[b * NCP + a]); }
                else        { pa = g_P[k][b * NCP + a]; qa = g_Q[k][b * NCP + a]; }

                float vqx = 0.f, vqy = 0.f, gpx = 0.f, gpy = 0.f;
#pragma unroll
                for (int half = 0; half < 2; half++) {
                    float z0 = half ? pj.x : pa.x, z1 = half ? pj.y : pa.y;
                    float z2 = half ? pa.x : pj.x, z3 = half ? pa.y : pj.y;
                    int da = half * 2, db = half * 2 + 1;
                    float o[3], ja[3], jb[3];
                    mlp_jac(z0, z1, z2, z3, da, db, hW1, hb1, hW2, hb2, hW3, hb3, o, ja, jb);
                    float ea = __expf(o[1]), eb = __expf(o[2]);
                    vqx += 0.5f * (ea * qj.x + o[0] * qj.y);
                    vqy += 0.5f * (o[0] * qj.x + eb * qj.y);
                    float cw = qa.x * qj.y + qa.y * qj.x;
                    float w1 = ea * (qa.x * qj.x), w2 = eb * (qa.y * qj.y);
                    gpx += 0.5f * (cw * ja[0] + w1 * ja[1] + w2 * ja[2]);
                    gpy += 0.5f * (cw * jb[0] + w1 * jb[1] + w2 * jb[2]);
                }
#pragma unroll
                for (int off = 16; off > 0; off >>= 1) {
                    vqx += __shfl_down_sync(0xffffffffu, vqx, off);
                    vqy += __shfl_down_sync(0xffffffffu, vqy, off);
                    gpx += __shfl_down_sync(0xffffffffu, gpx, off);
                    gpy += __shfl_down_sync(0xffffffffu, gpy, off);
                }
                if ((t & 31) == 0) {
                    red[aa][warp][0] = vqx; red[aa][warp][1] = vqy;
                    red[aa][warp][2] = gpx; red[aa][warp][3] = gpy;
                }
            }
            __syncthreads();
            if (t == 0) {
#pragma unroll
                for (int aa = 0; aa < 2; aa++) {
                    int a = a0 + aa;
                    float VX = red[aa][0][0] + red[aa][1][0];
                    float VY = red[aa][0][1] + red[aa][1][1];
                    float GX = red[aa][0][2] + red[aa][1][2];
                    float GY = red[aa][0][3] + red[aa][1][3];
                    float2 pa, qa;
                    if (k == 0) { pa = __ldg(&cp2[a]); qa = __ldg(&q02[b * NCP + a]); }
                    else        { pa = g_P[k][b * NCP + a]; qa = g_Q[k][b * NCP + a]; }
                    g_P[k + 1][b * NCP + a] = make_float2(pa.x + DTC * VX, pa.y + DTC * VY);
                    g_Q[k + 1][b * NCP + a] = make_float2(qa.x - DTC * GX, qa.y - DTC * GY);
                }
            }
            grid_bar_shoot();   // publishes g_bar_gen = k+1 (P/Q[k+1] ready)
        }
        return;
    }

    // ======================= FLOW ROLE =======================
    __shared__ ull sA[NCP][5];   // packed b1 + pj.W1[0:2]
    __shared__ ull sB[NCP][5];   // packed      pj.W1[2:4]
    __shared__ ull sQp[NCP];     // packed (0.5*qx, 0.5*qy)
    __shared__ float sW1[40], sb1[10];
    __shared__ float sW3c0[10];
    __shared__ ull sW3p12[10];
    __shared__ ull sb2p[5];
    int fbid = bid - SH_NCTA;
    int b = fbid >> 7;
    int pt0 = (fbid & 127) << 4;
    if (t < 40) sW1[t] = W1[t];
    if (t < 10) {
        sb1[t] = b1[t];
        sW3c0[t] = W3[t * 3 + 0];
        sW3p12[t] = pack2(LOG2E * W3[t * 3 + 1], LOG2E * W3[t * 3 + 2]);
    }
    if (t < 5) sb2p[t] = ((const ull*)b2)[t];

    const ull* W2v = (const ull*)W2;
    ull W2p[50];
#pragma unroll
    for (int i = 0; i < 50; i++) W2p[i] = __ldg(&W2v[i]);
    float b3c0 = __ldg(&b3[0]);
    ull b3p12 = pack2(LOG2E * __ldg(&b3[1]), LOG2E * __ldg(&b3[2]));

    int lp = t >> 2, quarter = t & 3;
    int i0 = pt0 + lp;
    float2 x = __ldg(&((const float2*)tpl)[i0]);

    for (int k = 0; k <= NSTEP; k++) {
        __syncthreads();   // prior iteration's reads of sA/sB done
        if (k > 0) {
            if (t == 0) {
                while (*(volatile unsigned*)&g_bar_gen < (unsigned)k) { __nanosleep(64); }
            }
            __syncthreads();   // all threads ordered after flag observation
        }
        {
            float2 p, q;
            if (k == 0) { p = __ldg(&cp2[t]); q = __ldg(&q02[b * NCP + t]); }
            else        { p = g_P[k][b * NCP + t]; q = g_Q[k][b * NCP + t]; }
#pragma unroll
            for (int i = 0; i < 5; i++) {
                int n0 = 2 * i, n1 = n0 + 1;
                sA[t][i] = pack2(sb1[n0] + p.x * sW1[n0] + p.y * sW1[10 + n0],
                                 sb1[n1] + p.x * sW1[n1] + p.y * sW1[10 + n1]);
                sB[t][i] = pack2(p.x * sW1[20 + n0] + p.y * sW1[30 + n0],
                                 p.x * sW1[20 + n1] + p.y * sW1[30 + n1]);
            }
            sQp[t] = pack2(0.5f * q.x, 0.5f * q.y);
        }
        ull axp[5], bxp[5];
#pragma unroll
        for (int i = 0; i < 5; i++) {
            int n0 = 2 * i, n1 = n0 + 1;
            axp[i] = pack2(sb1[n0] + x.x * sW1[n0] + x.y * sW1[10 + n0],
                           sb1[n1] + x.x * sW1[n1] + x.y * sW1[10 + n1]);
            bxp[i] = pack2(x.x * sW1[20 + n0] + x.y * sW1[30 + n0],
                           x.x * sW1[20 + n1] + x.y * sW1[30 + n1]);
        }
        __syncthreads();

        float vx = 0.f, vy = 0.f;
#pragma unroll 1
        for (int jj = 0; jj < 16; jj++) {
            int j = (jj << 2) | quarter;
            ull u1[5], u1c[5];
#pragma unroll
            for (int i = 0; i < 5; i++) u1[i] = add2(axp[i], sB[j][i]);   // m(x, pj)
            float a0v; ull a12;
            mlp2s(u1, W2p, sb2p, sW3c0, sW3p12, b3c0, b3p12, a0v, a12);
#pragma unroll
            for (int i = 0; i < 5; i++) u1c[i] = add2(sA[j][i], bxp[i]);  // m(pj, x)
            float c0v; ull c12;
            mlp2s(u1c, W2p, sb2p, sW3c0, sW3p12, b3c0, b3p12, c0v, c12);
            float a1, a2, c1, c2;
            unpack2(a12, a1, a2);
            unpack2(c12, c1, c2);
            float s0 = a0v + c0v;
            float qx2, qy2; unpack2(sQp[j], qx2, qy2);
            vx = fmaf(ex2f(a1), qx2, vx);
            vx = fmaf(ex2f(c1), qx2, vx);
            vx = fmaf(s0, qy2, vx);
            vy = fmaf(s0, qx2, vy);
            vy = fmaf(ex2f(a2), qy2, vy);
            vy = fmaf(ex2f(c2), qy2, vy);
        }
        vx += __shfl_xor_sync(0xffffffffu, vx, 1);
        vy += __shfl_xor_sync(0xffffffffu, vy, 1);
        vx += __shfl_xor_sync(0xffffffffu, vx, 2);
        vy += __shfl_xor_sync(0xffffffffu, vy, 2);
        x.x = fmaf(DTC, vx, x.x);
        x.y = fmaf(DTC, vy, x.y);
    }
    if (quarter == 0) ((float2*)dout)[b * NTPL + i0] = x;
}

// ------------------------------------------------------------------
extern "C" void kernel_launch(void* const* d_in, const int* in_sizes, int n_in,
                              void* d_out, int out_size) {
    const float* q0  = (const float*)d_in[0];
    const float* tpl = (const float*)d_in[1];
    const float* cp  = (const float*)d_in[2];
    const float* W1  = (const float*)d_in[3];
    const float* b1  = (const float*)d_in[4];
    const float* W2  = (const float*)d_in[5];
    const float* b2  = (const float*)d_in[6];
    const float* W3  = (const float*)d_in[7];
    const float* b3  = (const float*)d_in[8];
    float* out = (float*)d_out;
    (void)in_sizes; (void)n_in; (void)out_size;

    reset_kernel<<<1, 32>>>();
    fused_all<<<SH_NCTA + FL_NCTA, 64>>>(q0, tpl, cp, out,
                                         W1, b1, W2, b2, W3, b3);
}